// round 9
// baseline (speedup 1.0000x reference)
#include <cuda_runtime.h>
#include <cstdint>
#include <cstddef>

// ---------------- scratch (static __device__ arrays; no cudaMalloc) ----------------
static __device__ float  g_xchw[2 * 512 * 512];
static __device__ float  g_h1 [32 * 512 * 512];
static __device__ float  g_h2 [64 * 512 * 512];
static __device__ float  g_h2p[64 * 256 * 256];
static __device__ float  g_h3 [128 * 256 * 256];
static __device__ float  g_feat[128];
static __device__ float  g_u1[512];
static __device__ float  g_v1[512];
static __device__ float2 g_Ut[128 * 512];   // column-contiguous: [r][m]
static __device__ float2 g_Vt[128 * 512];

// ---------------- packed fp32x2 helpers (SASS FFMA2 — exact fp32, 2x throughput) ----
__device__ __forceinline__ unsigned long long pack2(float lo, float hi) {
    unsigned long long r;
    asm("mov.b64 %0, {%1, %2};" : "=l"(r) : "f"(lo), "f"(hi));
    return r;
}
__device__ __forceinline__ float2 unpack2(unsigned long long v) {
    float2 r;
    asm("mov.b64 {%0, %1}, %2;" : "=f"(r.x), "=f"(r.y) : "l"(v));
    return r;
}
__device__ __forceinline__ void fma2(unsigned long long& d, unsigned long long a,
                                     unsigned long long b) {
    asm("fma.rn.f32x2 %0, %1, %2, %0;" : "+l"(d) : "l"(a), "l"(b));
}

// ---------------- (H,W,2) -> CHW transpose ----------------
__global__ void prep_x_kernel(const float* __restrict__ x, float* __restrict__ xchw) {
    int idx = blockIdx.x * 256 + threadIdx.x;   // 512*512 exactly
    float2 v = reinterpret_cast<const float2*>(x)[idx];
    xchw[idx] = v.x;
    xchw[512 * 512 + idx] = v.y;
}

// ---------------- direct 3x3 conv (pad=1) + bias + ReLU, packed f32x2 ----------------
// block = 128 threads: og = tid>>6 (8 out-ch each), pg = tid&63 (4 px each)
// tile = 16 output channels x 256 pixels (one partial row)
template<int CIN>
__global__ __launch_bounds__(128)
void conv3x3_relu(const float* __restrict__ in, const float* __restrict__ wt,
                  const float* __restrict__ bias, float* __restrict__ out,
                  int H, int W) {
    extern __shared__ unsigned long long sw2[];        // 16 * CIN * 9 duplicated pairs
    const int tid = threadIdx.x;
    const int obase = blockIdx.z * 16;
    for (int idx = tid; idx < 16 * CIN * 9; idx += 128) {
        float w = wt[obase * CIN * 9 + idx];
        sw2[idx] = pack2(w, w);
    }
    __syncthreads();

    const int og = tid >> 6;                 // warp-uniform
    const int pg = tid & 63;
    const int h  = blockIdx.y;
    const int x0 = blockIdx.x * 256 + pg * 4;

    unsigned long long acc[8][2];
#pragma unroll
    for (int a = 0; a < 8; ++a) { acc[a][0] = 0ull; acc[a][1] = 0ull; }

    const int NSEG = CIN * 3;
    float rn[6];
    {   // prefetch segment 0 (c=0, ky=0)
        int y = h - 1;
        bool yv = ((unsigned)y < (unsigned)H);
        const float* ip = in + (size_t)y * W;
#pragma unroll
        for (int dx = 0; dx < 6; ++dx) {
            int xx = x0 - 1 + dx;
            rn[dx] = (yv && (unsigned)xx < (unsigned)W) ? __ldg(ip + xx) : 0.f;
        }
    }

#pragma unroll 1
    for (int seg = 0; seg < NSEG; ++seg) {
        float r[6];
#pragma unroll
        for (int d = 0; d < 6; ++d) r[d] = rn[d];

        if (seg + 1 < NSEG) {               // prefetch next segment while computing
            int s1 = seg + 1;
            int c = s1 / 3, ky = s1 % 3;
            int y = h + ky - 1;
            bool yv = ((unsigned)y < (unsigned)H);
            const float* ip = in + ((size_t)c * H + y) * W;
#pragma unroll
            for (int dx = 0; dx < 6; ++dx) {
                int xx = x0 - 1 + dx;
                rn[dx] = (yv && (unsigned)xx < (unsigned)W) ? __ldg(ip + xx) : 0.f;
            }
        }

        unsigned long long pa[3] = { pack2(r[0], r[1]), pack2(r[1], r[2]), pack2(r[2], r[3]) };
        unsigned long long pb[3] = { pack2(r[2], r[3]), pack2(r[3], r[4]), pack2(r[4], r[5]) };
        const unsigned long long* swp = sw2 + (og * 8) * (CIN * 9) + seg * 3;  // = c*9+ky*3
#pragma unroll
        for (int kx = 0; kx < 3; ++kx) {
#pragma unroll
            for (int oo = 0; oo < 8; ++oo) {
                unsigned long long w2 = swp[oo * (CIN * 9) + kx];  // LDS.64 broadcast
                fma2(acc[oo][0], w2, pa[kx]);
                fma2(acc[oo][1], w2, pb[kx]);
            }
        }
    }

#pragma unroll
    for (int oo = 0; oo < 8; ++oo) {
        const int o = obase + og * 8 + oo;
        const float b = bias[o];
        float2 v0 = unpack2(acc[oo][0]);
        float2 v1 = unpack2(acc[oo][1]);
        float4 res;
        res.x = fmaxf(v0.x + b, 0.f); res.y = fmaxf(v0.y + b, 0.f);
        res.z = fmaxf(v1.x + b, 0.f); res.w = fmaxf(v1.y + b, 0.f);
        *reinterpret_cast<float4*>(out + ((size_t)o * H + h) * W + x0) = res;
    }
}

// ---------------- 2x2 maxpool stride 2 (64ch, 512 -> 256) ----------------
__global__ void maxpool2_kernel(const float* __restrict__ in, float* __restrict__ out) {
    int idx = blockIdx.x * 256 + threadIdx.x;   // 64*256*256 exactly
    int x = idx & 255, y = (idx >> 8) & 255, c = idx >> 16;
    const float* p = in + ((size_t)c * 512 + 2 * y) * 512 + 2 * x;
    out[idx] = fmaxf(fmaxf(p[0], p[1]), fmaxf(p[512], p[513]));
}

// ---------------- global average pool: 128 channels of 256x256 ----------------
__global__ void avgpool_kernel(const float* __restrict__ in, float* __restrict__ feat) {
    const int c = blockIdx.x;
    const float* p = in + (size_t)c * 65536;
    float s = 0.f;
    for (int i = threadIdx.x; i < 65536; i += 256) s += p[i];
    __shared__ float sh[256];
    sh[threadIdx.x] = s;
    __syncthreads();
    for (int off = 128; off > 0; off >>= 1) {
        if (threadIdx.x < off) sh[threadIdx.x] += sh[threadIdx.x + off];
        __syncthreads();
    }
    if (threadIdx.x == 0) feat[c] = sh[0] * (1.f / 65536.f);
}

// ---------------- fused small FC trunk + s head (softplus+sort) + u1/v1 ----------------
__device__ __forceinline__ float dot4(const float* __restrict__ w,
                                      const float* __restrict__ v, int n4) {
    float a = 0.f;
    const float4* w4 = (const float4*)w;
    const float4* v4 = (const float4*)v;
#pragma unroll 8
    for (int k = 0; k < n4; ++k) {
        float4 ww = w4[k], vv = v4[k];
        a += ww.x * vv.x + ww.y * vv.y + ww.z * vv.z + ww.w * vv.w;
    }
    return a;
}

__global__ __launch_bounds__(512)
void small_layers_kernel(const float* __restrict__ feat,
    const float* __restrict__ fw1, const float* __restrict__ fb1,
    const float* __restrict__ fw2, const float* __restrict__ fb2,
    const float* __restrict__ sw1, const float* __restrict__ sb1,
    const float* __restrict__ sw2, const float* __restrict__ sb2,
    const float* __restrict__ uw1, const float* __restrict__ ub1,
    const float* __restrict__ vw1, const float* __restrict__ vb1,
    float* __restrict__ u1g, float* __restrict__ v1g, float* __restrict__ s_out) {
    __shared__ __align__(16) float sf[128];
    __shared__ __align__(16) float f1[256];
    __shared__ __align__(16) float f2[512];
    __shared__ __align__(16) float s1[256];
    __shared__ float sv[128];
    const int t = threadIdx.x;

    if (t < 128) sf[t] = feat[t];
    __syncthreads();

    if (t < 256) f1[t] = fmaxf(fb1[t] + dot4(fw1 + t * 128, sf, 32), 0.f);
    __syncthreads();

    f2[t] = fmaxf(fb2[t] + dot4(fw2 + t * 256, f1, 64), 0.f);
    __syncthreads();

    if (t < 256) s1[t] = fmaxf(sb1[t] + dot4(sw1 + (size_t)t * 512, f2, 128), 0.f);
    __syncthreads();

    if (t < 128) {
        float xv = sb2[t] + dot4(sw2 + t * 256, s1, 64);
        sv[t] = (xv > 0.f) ? (xv + log1pf(expf(-xv))) : log1pf(expf(xv));
    }
    __syncthreads();

    // descending sort by rank (ties: later original index first, matching sort+reverse)
    if (t < 128) {
        float v = sv[t];
        int rank = 0;
        for (int j = 0; j < 128; ++j) {
            float o = sv[j];
            rank += (o > v) || (o == v && j > t);
        }
        s_out[rank] = v;
    }

    u1g[t] = fmaxf(ub1[t] + dot4(uw1 + (size_t)t * 512, f2, 128), 0.f);
    v1g[t] = fmaxf(vb1[t] + dot4(vw1 + (size_t)t * 512, f2, 128), 0.f);
}

// ---------------- big head matvecs: 2 x (131072 x 512), write transposed ----------------
__global__ __launch_bounds__(256)
void big_head_kernel(const float* __restrict__ uw2, const float* __restrict__ ub2,
                     const float* __restrict__ vw2, const float* __restrict__ vb2,
                     const float* __restrict__ u1, const float* __restrict__ v1,
                     float* __restrict__ Ut, float* __restrict__ Vt) {
    __shared__ __align__(16) float su[512];
    __shared__ __align__(16) float svv[512];
    const int t = threadIdx.x;
    for (int i = t; i < 512; i += 256) { su[i] = u1[i]; svv[i] = v1[i]; }
    __syncthreads();

    const int lane = t & 31, warp = t >> 5;
    const int gw = blockIdx.x * 8 + warp;           // 16384 warps total
#pragma unroll 1
    for (int rr = 0; rr < 16; ++rr) {
        int e = gw * 16 + rr;                       // 0..262143
        const float* wrow; const float* xv; float b; float* dst;
        if (e < 131072) {
            wrow = uw2 + (size_t)e * 512; xv = su; b = ub2[e];
            int m = e >> 8, r = (e >> 1) & 127, cp = e & 1;
            dst = Ut + (size_t)(r * 512 + m) * 2 + cp;
        } else {
            int e2 = e - 131072;
            wrow = vw2 + (size_t)e2 * 512; xv = svv; b = vb2[e2];
            int m = e2 >> 8, r = (e2 >> 1) & 127, cp = e2 & 1;
            dst = Vt + (size_t)(r * 512 + m) * 2 + cp;
        }
        float a = 0.f;
        const float4* w4 = (const float4*)wrow;
        const float4* x4 = (const float4*)xv;
#pragma unroll
        for (int k = lane; k < 128; k += 32) {
            float4 ww = w4[k], vv = x4[k];
            a += ww.x * vv.x + ww.y * vv.y + ww.z * vv.z + ww.w * vv.w;
        }
#pragma unroll
        for (int off = 16; off; off >>= 1) a += __shfl_down_sync(0xffffffffu, a, off);
        if (lane == 0) *dst = a + b;
    }
}

// ---------------- right-looking MGS, single-pass registers, fused normalize ----------
// block 0: U, block 1: V. 1024 threads. Matrix is column-contiguous float2[128][512].
// Per iteration: ONE barrier. The warp owning column i+1 also normalizes it and
// publishes q_{i+1} into a double-buffered shared array.
__global__ __launch_bounds__(1024)
void gs_kernel(float2* __restrict__ Ut, float2* __restrict__ Vt, float* __restrict__ out) {
    float2* Vm = (blockIdx.x == 0) ? Ut : Vt;
    float2* outp = (float2*)(out + ((blockIdx.x == 0) ? 0 : (131072 + 128)));
    __shared__ float2 q[2][512];
    __shared__ float red[32];
    __shared__ float s_inv;
    const int t = threadIdx.x;
    const int lane = t & 31, warp = t >> 5;

    // ---- finalize column 0 (block-wide) ----
    {
        float2 v = make_float2(0.f, 0.f);
        float nr = 0.f;
        if (t < 512) { v = Vm[t]; nr = v.x * v.x + v.y * v.y; }
#pragma unroll
        for (int off = 16; off; off >>= 1) nr += __shfl_down_sync(0xffffffffu, nr, off);
        if (lane == 0) red[warp] = nr;
        __syncthreads();
        if (warp == 0) {
            float s = red[lane];
#pragma unroll
            for (int off = 16; off; off >>= 1) s += __shfl_down_sync(0xffffffffu, s, off);
            if (lane == 0) s_inv = 1.f / sqrtf(s + 1e-8f);
        }
        __syncthreads();
        if (t < 512) {
            float inv = s_inv;
            float2 qv = make_float2(v.x * inv, v.y * inv);
            q[0][t] = qv;
            outp[t * 128] = qv;                   // column 0 in (m, r) float2 layout
        }
        __syncthreads();
    }

#pragma unroll 1
    for (int i = 0; i < 127; ++i) {
        const float2* qc = q[i & 1];
        float2* qn = q[(i + 1) & 1];
        for (int j = i + 1 + warp; j < 128; j += 32) {
            float2* col = Vm + j * 512;
            float2 vv[16];
#pragma unroll
            for (int k = 0; k < 16; ++k) vv[k] = col[lane + 32 * k];   // single load pass
            float cr = 0.f, ci = 0.f;
#pragma unroll
            for (int k = 0; k < 16; ++k) {
                float2 qm = qc[lane + 32 * k];
                cr += qm.x * vv[k].x + qm.y * vv[k].y;                 // conj(q) * v
                ci += qm.x * vv[k].y - qm.y * vv[k].x;
            }
#pragma unroll
            for (int off = 16; off; off >>= 1) {
                cr += __shfl_xor_sync(0xffffffffu, cr, off);
                ci += __shfl_xor_sync(0xffffffffu, ci, off);
            }
            if (j == i + 1) {
                // update + normalize + publish q_{i+1}, no writeback to Vm needed
                float nr = 0.f;
#pragma unroll
                for (int k = 0; k < 16; ++k) {
                    float2 qm = qc[lane + 32 * k];
                    vv[k].x -= cr * qm.x - ci * qm.y;
                    vv[k].y -= cr * qm.y + ci * qm.x;
                    nr += vv[k].x * vv[k].x + vv[k].y * vv[k].y;
                }
#pragma unroll
                for (int off = 16; off; off >>= 1) nr += __shfl_xor_sync(0xffffffffu, nr, off);
                float inv = 1.f / sqrtf(nr + 1e-8f);
#pragma unroll
                for (int k = 0; k < 16; ++k) {
                    int m = lane + 32 * k;
                    float2 qv = make_float2(vv[k].x * inv, vv[k].y * inv);
                    qn[m] = qv;
                    outp[m * 128 + (i + 1)] = qv;
                }
            } else {
#pragma unroll
                for (int k = 0; k < 16; ++k) {
                    float2 qm = qc[lane + 32 * k];
                    vv[k].x -= cr * qm.x - ci * qm.y;
                    vv[k].y -= cr * qm.y + ci * qm.x;
                    col[lane + 32 * k] = vv[k];                        // single store pass
                }
            }
        }
        __syncthreads();
    }
}

// ---------------- launch ----------------
extern "C" void kernel_launch(void* const* d_in, const int* in_sizes, int n_in,
                              void* d_out, int out_size) {
    const float* x   = (const float*)d_in[0];
    const float* cw1 = (const float*)d_in[1];  const float* cb1 = (const float*)d_in[2];
    const float* cw2 = (const float*)d_in[3];  const float* cb2 = (const float*)d_in[4];
    const float* cw3 = (const float*)d_in[5];  const float* cb3 = (const float*)d_in[6];
    const float* fw1 = (const float*)d_in[7];  const float* fb1 = (const float*)d_in[8];
    const float* fw2 = (const float*)d_in[9];  const float* fb2 = (const float*)d_in[10];
    const float* sw1 = (const float*)d_in[11]; const float* sb1 = (const float*)d_in[12];
    const float* sw2 = (const float*)d_in[13]; const float* sb2 = (const float*)d_in[14];
    const float* uw1 = (const float*)d_in[15]; const float* ub1 = (const float*)d_in[16];
    const float* uw2 = (const float*)d_in[17]; const float* ub2 = (const float*)d_in[18];
    const float* vw1 = (const float*)d_in[19]; const float* vb1 = (const float*)d_in[20];
    const float* vw2 = (const float*)d_in[21]; const float* vb2 = (const float*)d_in[22];
    float* out = (float*)d_out;

    float *xchw, *h1, *h2, *h2p, *h3, *feat, *u1, *v1;
    float2 *Ut, *Vt;
    cudaGetSymbolAddress((void**)&xchw, g_xchw);
    cudaGetSymbolAddress((void**)&h1,   g_h1);
    cudaGetSymbolAddress((void**)&h2,   g_h2);
    cudaGetSymbolAddress((void**)&h2p,  g_h2p);
    cudaGetSymbolAddress((void**)&h3,   g_h3);
    cudaGetSymbolAddress((void**)&feat, g_feat);
    cudaGetSymbolAddress((void**)&u1,   g_u1);
    cudaGetSymbolAddress((void**)&v1,   g_v1);
    cudaGetSymbolAddress((void**)&Ut,   g_Ut);
    cudaGetSymbolAddress((void**)&Vt,   g_Vt);

    // conv3 needs 72 KB dynamic smem (> 48 KB default)
    cudaFuncSetAttribute(conv3x3_relu<64>, cudaFuncAttributeMaxDynamicSharedMemorySize,
                         16 * 64 * 9 * 8);

    prep_x_kernel<<<1024, 256>>>(x, xchw);
    conv3x3_relu<2> <<<dim3(2, 512, 2), 128, 16 * 2  * 9 * 8>>>(xchw, cw1, cb1, h1, 512, 512);
    conv3x3_relu<32><<<dim3(2, 512, 4), 128, 16 * 32 * 9 * 8>>>(h1,   cw2, cb2, h2, 512, 512);
    maxpool2_kernel<<<16384, 256>>>(h2, h2p);
    conv3x3_relu<64><<<dim3(1, 256, 8), 128, 16 * 64 * 9 * 8>>>(h2p,  cw3, cb3, h3, 256, 256);
    avgpool_kernel<<<128, 256>>>(h3, feat);
    small_layers_kernel<<<1, 512>>>(feat, fw1, fb1, fw2, fb2, sw1, sb1, sw2, sb2,
                                    uw1, ub1, vw1, vb1, u1, v1, out + 131072);
    big_head_kernel<<<2048, 256>>>(uw2, ub2, vw2, vb2, u1, v1, (float*)Ut, (float*)Vt);
    gs_kernel<<<2, 1024>>>(Ut, Vt, out);
}

// round 10
// speedup vs baseline: 1.1935x; 1.1935x over previous
#include <cuda_runtime.h>
#include <cstdint>
#include <cstddef>

// ---------------- scratch (static __device__ arrays; no cudaMalloc) ----------------
static __device__ float  g_xchw[2 * 512 * 512];
static __device__ float  g_h1 [32 * 512 * 512];
static __device__ float  g_h2 [64 * 512 * 512];
static __device__ float  g_h2p[64 * 256 * 256];
static __device__ float  g_h3 [128 * 256 * 256];
static __device__ float  g_feat[128];
static __device__ float  g_u1[512];
static __device__ float  g_v1[512];
static __device__ float2 g_Ut[128 * 512];   // column-contiguous: [r][m]
static __device__ float2 g_Vt[128 * 512];

// ---------------- (H,W,2) -> CHW transpose ----------------
__global__ void prep_x_kernel(const float* __restrict__ x, float* __restrict__ xchw) {
    int idx = blockIdx.x * 256 + threadIdx.x;   // 512*512 exactly
    float2 v = reinterpret_cast<const float2*>(x)[idx];
    xchw[idx] = v.x;
    xchw[512 * 512 + idx] = v.y;
}

// ---------------- scalar direct conv (used only for tiny conv1, CIN=2) ------------
template<int CIN>
__global__ __launch_bounds__(128)
void conv3x3_relu(const float* __restrict__ in, const float* __restrict__ wt,
                  const float* __restrict__ bias, float* __restrict__ out,
                  int H, int W) {
    extern __shared__ float sw[];               // 16 * CIN * 9 floats
    const int tid = threadIdx.x;
    const int obase = blockIdx.z * 16;
    for (int idx = tid; idx < 16 * CIN * 9; idx += 128)
        sw[idx] = wt[obase * CIN * 9 + idx];
    __syncthreads();

    const int og = tid >> 6;
    const int pg = tid & 63;
    const int h  = blockIdx.y;
    const int x0 = blockIdx.x * 256 + pg * 4;

    float acc[8][4];
#pragma unroll
    for (int a = 0; a < 8; ++a)
#pragma unroll
        for (int p = 0; p < 4; ++p) acc[a][p] = 0.f;

#pragma unroll
    for (int c = 0; c < CIN; ++c) {
#pragma unroll
        for (int ky = 0; ky < 3; ++ky) {
            const int yy = h + ky - 1;
            const bool yv = ((unsigned)yy < (unsigned)H);
            const float* ip = in + ((size_t)c * H + yy) * W;
            float r[6];
#pragma unroll
            for (int dx = 0; dx < 6; ++dx) {
                int xx = x0 - 1 + dx;
                r[dx] = (yv && (unsigned)xx < (unsigned)W) ? __ldg(ip + xx) : 0.f;
            }
            const float* swp = sw + (og * 8) * (CIN * 9) + c * 9 + ky * 3;
#pragma unroll
            for (int kx = 0; kx < 3; ++kx) {
#pragma unroll
                for (int oo = 0; oo < 8; ++oo) {
                    float wv = swp[oo * (CIN * 9) + kx];
                    acc[oo][0] = fmaf(wv, r[kx + 0], acc[oo][0]);
                    acc[oo][1] = fmaf(wv, r[kx + 1], acc[oo][1]);
                    acc[oo][2] = fmaf(wv, r[kx + 2], acc[oo][2]);
                    acc[oo][3] = fmaf(wv, r[kx + 3], acc[oo][3]);
                }
            }
        }
    }
#pragma unroll
    for (int oo = 0; oo < 8; ++oo) {
        const int o = obase + og * 8 + oo;
        const float b = bias[o];
        float4 res;
        res.x = fmaxf(acc[oo][0] + b, 0.f); res.y = fmaxf(acc[oo][1] + b, 0.f);
        res.z = fmaxf(acc[oo][2] + b, 0.f); res.w = fmaxf(acc[oo][3] + b, 0.f);
        *reinterpret_cast<float4*>(out + ((size_t)o * H + h) * W + x0) = res;
    }
}

// ---------------- tf32 3-term tensor-core conv (exact-to-fp32 precision) ----------
// Block: 256 threads = 8 warps (4 M-warps x 2 N-warps).
// Tile: 64 out-channels x 128 pixels of one output row. K-loop: (CIN/8) chunks x 9 shifts.
// Error analysis: W = Whi+Wlo, X = Xhi+Xlo (tf32 splits); D += WhiXhi + WloXhi + WhiXlo
// leaves only the Wlo*Xlo term (~2^-22 rel) -> fp32-equivalent output.

__device__ __forceinline__ float tf32r(float v) {
    uint32_t r;
    asm("cvt.rna.tf32.f32 %0, %1;" : "=r"(r) : "f"(v));
    return __uint_as_float(r);
}
__device__ __forceinline__ void mma_tf32(float* c, uint32_t a0, uint32_t a1,
                                         uint32_t a2, uint32_t a3,
                                         uint32_t b0, uint32_t b1) {
    asm volatile(
        "mma.sync.aligned.m16n8k8.row.col.f32.tf32.tf32.f32 "
        "{%0,%1,%2,%3}, {%4,%5,%6,%7}, {%8,%9}, {%0,%1,%2,%3};"
        : "+f"(c[0]), "+f"(c[1]), "+f"(c[2]), "+f"(c[3])
        : "r"(a0), "r"(a1), "r"(a2), "r"(a3), "r"(b0), "r"(b1));
}
__device__ __forceinline__ uint32_t fbits(float v) { return __float_as_uint(v); }

// smem layout (floats):
//   xh [3][130][12]  (12 = 8 channels + 4 pad, conflict-free B loads)   0     .. 4679
//   xl                                                                   4680  .. 9359
//   wh [64][76]      (76 = 9*8 + 4 pad, conflict-free A loads)          9360  .. 14223
//   wl                                                                   14224 .. 19087
#define CMM_SMEM_FLOATS 19088

template<int CIN>
__global__ __launch_bounds__(256)
void conv3x3_mma(const float* __restrict__ in, const float* __restrict__ wt,
                 const float* __restrict__ bias, float* __restrict__ out,
                 int H, int W) {
    extern __shared__ float sm[];
    float* xh = sm;
    float* xl = sm + 4680;
    float* wh = sm + 9360;
    float* wl = sm + 14224;

    const int t = threadIdx.x;
    const int lane = t & 31, warp = t >> 5;
    const int g = lane >> 2, tg = lane & 3;
    const int mwarp = warp & 3, nwarp = warp >> 2;
    const int x0 = blockIdx.x * 128;
    const int y  = blockIdx.y;
    const int obase = blockIdx.z * 64;

    float acc[8][4];
#pragma unroll
    for (int nt = 0; nt < 8; ++nt)
#pragma unroll
        for (int i = 0; i < 4; ++i) acc[nt][i] = 0.f;

#pragma unroll 1
    for (int c0 = 0; c0 < CIN / 8; ++c0) {
        __syncthreads();
        // ---- load + split X slab: 8 ch x 3 rows x 130 px (zero-padded at edges) ----
        for (int idx = t; idx < 3120; idx += 256) {
            int c  = idx / 390;
            int rr = idx - c * 390;
            int r  = rr / 130, x = rr - r * 130;
            int yy = y + r - 1, xx = x0 + x - 1;
            float v = 0.f;
            if ((unsigned)yy < (unsigned)H && (unsigned)xx < (unsigned)W)
                v = __ldg(in + ((size_t)(c0 * 8 + c) * H + yy) * W + xx);
            float hi = tf32r(v);
            float lo = tf32r(v - hi);
            int o = (r * 130 + x) * 12 + c;
            xh[o] = hi; xl[o] = lo;
        }
        // ---- load + split W slab: 64 out x 9 shifts x 8 ch ----
        for (int idx = t; idx < 4608; idx += 256) {
            int o = idx / 72, r = idx - o * 72;
            int s = r >> 3, k = r & 7;
            float v = __ldg(wt + ((size_t)(obase + o) * CIN + c0 * 8 + k) * 9 + s);
            float hi = tf32r(v);
            float lo = tf32r(v - hi);
            wh[o * 76 + s * 8 + k] = hi;
            wl[o * 76 + s * 8 + k] = lo;
        }
        __syncthreads();

#pragma unroll
        for (int ky = 0; ky < 3; ++ky) {
#pragma unroll
            for (int kx = 0; kx < 3; ++kx) {
                const int s = ky * 3 + kx;
                const float* pwh = wh + (mwarp * 16 + g) * 76 + s * 8 + tg;
                const float* pwl = wl + (mwarp * 16 + g) * 76 + s * 8 + tg;
                uint32_t a0h = fbits(pwh[0]),      a2h = fbits(pwh[4]);
                uint32_t a1h = fbits(pwh[8 * 76]), a3h = fbits(pwh[8 * 76 + 4]);
                uint32_t a0l = fbits(pwl[0]),      a2l = fbits(pwl[4]);
                uint32_t a1l = fbits(pwl[8 * 76]), a3l = fbits(pwl[8 * 76 + 4]);
                const int xbase = (ky * 130 + nwarp * 64 + g + kx) * 12 + tg;
#pragma unroll
                for (int nt = 0; nt < 8; ++nt) {
                    const int ib = xbase + nt * 8 * 12;
                    uint32_t b0h = fbits(xh[ib]), b1h = fbits(xh[ib + 4]);
                    uint32_t b0l = fbits(xl[ib]), b1l = fbits(xl[ib + 4]);
                    mma_tf32(acc[nt], a0h, a1h, a2h, a3h, b0h, b1h);
                    mma_tf32(acc[nt], a0l, a1l, a2l, a3l, b0h, b1h);
                    mma_tf32(acc[nt], a0h, a1h, a2h, a3h, b0l, b1l);
                }
            }
        }
    }

    // ---- epilogue: bias + relu, direct float2 stores ----
    const int o_lo = obase + mwarp * 16 + g;
    const float b_lo = __ldg(bias + o_lo);
    const float b_hi = __ldg(bias + o_lo + 8);
    float* row_lo = out + ((size_t)o_lo * H + y) * W;
    float* row_hi = out + ((size_t)(o_lo + 8) * H + y) * W;
#pragma unroll
    for (int nt = 0; nt < 8; ++nt) {
        int x = x0 + nwarp * 64 + nt * 8 + 2 * tg;
        float2 v0 = make_float2(fmaxf(acc[nt][0] + b_lo, 0.f),
                                fmaxf(acc[nt][1] + b_lo, 0.f));
        float2 v1 = make_float2(fmaxf(acc[nt][2] + b_hi, 0.f),
                                fmaxf(acc[nt][3] + b_hi, 0.f));
        *reinterpret_cast<float2*>(row_lo + x) = v0;
        *reinterpret_cast<float2*>(row_hi + x) = v1;
    }
}

// ---------------- 2x2 maxpool stride 2 (64ch, 512 -> 256) ----------------
__global__ void maxpool2_kernel(const float* __restrict__ in, float* __restrict__ out) {
    int idx = blockIdx.x * 256 + threadIdx.x;   // 64*256*256 exactly
    int x = idx & 255, y = (idx >> 8) & 255, c = idx >> 16;
    const float* p = in + ((size_t)c * 512 + 2 * y) * 512 + 2 * x;
    out[idx] = fmaxf(fmaxf(p[0], p[1]), fmaxf(p[512], p[513]));
}

// ---------------- global average pool: 128 channels of 256x256 ----------------
__global__ void avgpool_kernel(const float* __restrict__ in, float* __restrict__ feat) {
    const int c = blockIdx.x;
    const float* p = in + (size_t)c * 65536;
    float s = 0.f;
    for (int i = threadIdx.x; i < 65536; i += 256) s += p[i];
    __shared__ float sh[256];
    sh[threadIdx.x] = s;
    __syncthreads();
    for (int off = 128; off > 0; off >>= 1) {
        if (threadIdx.x < off) sh[threadIdx.x] += sh[threadIdx.x + off];
        __syncthreads();
    }
    if (threadIdx.x == 0) feat[c] = sh[0] * (1.f / 65536.f);
}

// ---------------- fused small FC trunk + s head (softplus+sort) + u1/v1 ----------------
__device__ __forceinline__ float dot4(const float* __restrict__ w,
                                      const float* __restrict__ v, int n4) {
    float a = 0.f;
    const float4* w4 = (const float4*)w;
    const float4* v4 = (const float4*)v;
#pragma unroll 8
    for (int k = 0; k < n4; ++k) {
        float4 ww = w4[k], vv = v4[k];
        a += ww.x * vv.x + ww.y * vv.y + ww.z * vv.z + ww.w * vv.w;
    }
    return a;
}

__global__ __launch_bounds__(512)
void small_layers_kernel(const float* __restrict__ feat,
    const float* __restrict__ fw1, const float* __restrict__ fb1,
    const float* __restrict__ fw2, const float* __restrict__ fb2,
    const float* __restrict__ sw1, const float* __restrict__ sb1,
    const float* __restrict__ sw2, const float* __restrict__ sb2,
    const float* __restrict__ uw1, const float* __restrict__ ub1,
    const float* __restrict__ vw1, const float* __restrict__ vb1,
    float* __restrict__ u1g, float* __restrict__ v1g, float* __restrict__ s_out) {
    __shared__ __align__(16) float sf[128];
    __shared__ __align__(16) float f1[256];
    __shared__ __align__(16) float f2[512];
    __shared__ __align__(16) float s1[256];
    __shared__ float sv[128];
    const int t = threadIdx.x;

    if (t < 128) sf[t] = feat[t];
    __syncthreads();

    if (t < 256) f1[t] = fmaxf(fb1[t] + dot4(fw1 + t * 128, sf, 32), 0.f);
    __syncthreads();

    f2[t] = fmaxf(fb2[t] + dot4(fw2 + t * 256, f1, 64), 0.f);
    __syncthreads();

    if (t < 256) s1[t] = fmaxf(sb1[t] + dot4(sw1 + (size_t)t * 512, f2, 128), 0.f);
    __syncthreads();

    if (t < 128) {
        float xv = sb2[t] + dot4(sw2 + t * 256, s1, 64);
        sv[t] = (xv > 0.f) ? (xv + log1pf(expf(-xv))) : log1pf(expf(xv));
    }
    __syncthreads();

    // descending sort by rank (ties: later original index first, matching sort+reverse)
    if (t < 128) {
        float v = sv[t];
        int rank = 0;
        for (int j = 0; j < 128; ++j) {
            float o = sv[j];
            rank += (o > v) || (o == v && j > t);
        }
        s_out[rank] = v;
    }

    u1g[t] = fmaxf(ub1[t] + dot4(uw1 + (size_t)t * 512, f2, 128), 0.f);
    v1g[t] = fmaxf(vb1[t] + dot4(vw1 + (size_t)t * 512, f2, 128), 0.f);
}

// ---------------- big head matvecs: 2 x (131072 x 512), write transposed ----------------
__global__ __launch_bounds__(256)
void big_head_kernel(const float* __restrict__ uw2, const float* __restrict__ ub2,
                     const float* __restrict__ vw2, const float* __restrict__ vb2,
                     const float* __restrict__ u1, const float* __restrict__ v1,
                     float* __restrict__ Ut, float* __restrict__ Vt) {
    __shared__ __align__(16) float su[512];
    __shared__ __align__(16) float svv[512];
    const int t = threadIdx.x;
    for (int i = t; i < 512; i += 256) { su[i] = u1[i]; svv[i] = v1[i]; }
    __syncthreads();

    const int lane = t & 31, warp = t >> 5;
    const int gw = blockIdx.x * 8 + warp;           // 16384 warps total
#pragma unroll 1
    for (int rr = 0; rr < 16; ++rr) {
        int e = gw * 16 + rr;                       // 0..262143
        const float* wrow; const float* xv; float b; float* dst;
        if (e < 131072) {
            wrow = uw2 + (size_t)e * 512; xv = su; b = ub2[e];
            int m = e >> 8, r = (e >> 1) & 127, cp = e & 1;
            dst = Ut + (size_t)(r * 512 + m) * 2 + cp;
        } else {
            int e2 = e - 131072;
            wrow = vw2 + (size_t)e2 * 512; xv = svv; b = vb2[e2];
            int m = e2 >> 8, r = (e2 >> 1) & 127, cp = e2 & 1;
            dst = Vt + (size_t)(r * 512 + m) * 2 + cp;
        }
        float a = 0.f;
        const float4* w4 = (const float4*)wrow;
        const float4* x4 = (const float4*)xv;
#pragma unroll
        for (int k = lane; k < 128; k += 32) {
            float4 ww = w4[k], vv = x4[k];
            a += ww.x * vv.x + ww.y * vv.y + ww.z * vv.z + ww.w * vv.w;
        }
#pragma unroll
        for (int off = 16; off; off >>= 1) a += __shfl_down_sync(0xffffffffu, a, off);
        if (lane == 0) *dst = a + b;
    }
}

// ---------------- right-looking MGS, single-pass registers, fused normalize ----------
__global__ __launch_bounds__(1024)
void gs_kernel(float2* __restrict__ Ut, float2* __restrict__ Vt, float* __restrict__ out) {
    float2* Vm = (blockIdx.x == 0) ? Ut : Vt;
    float2* outp = (float2*)(out + ((blockIdx.x == 0) ? 0 : (131072 + 128)));
    __shared__ float2 q[2][512];
    __shared__ float red[32];
    __shared__ float s_inv;
    const int t = threadIdx.x;
    const int lane = t & 31, warp = t >> 5;

    // ---- finalize column 0 (block-wide) ----
    {
        float2 v = make_float2(0.f, 0.f);
        float nr = 0.f;
        if (t < 512) { v = Vm[t]; nr = v.x * v.x + v.y * v.y; }
#pragma unroll
        for (int off = 16; off; off >>= 1) nr += __shfl_down_sync(0xffffffffu, nr, off);
        if (lane == 0) red[warp] = nr;
        __syncthreads();
        if (warp == 0) {
            float s = red[lane];
#pragma unroll
            for (int off = 16; off; off >>= 1) s += __shfl_down_sync(0xffffffffu, s, off);
            if (lane == 0) s_inv = 1.f / sqrtf(s + 1e-8f);
        }
        __syncthreads();
        if (t < 512) {
            float inv = s_inv;
            float2 qv = make_float2(v.x * inv, v.y * inv);
            q[0][t] = qv;
            outp[t * 128] = qv;
        }
        __syncthreads();
    }

#pragma unroll 1
    for (int i = 0; i < 127; ++i) {
        const float2* qc = q[i & 1];
        float2* qn = q[(i + 1) & 1];
        for (int j = i + 1 + warp; j < 128; j += 32) {
            float2* col = Vm + j * 512;
            float2 vv[16];
#pragma unroll
            for (int k = 0; k < 16; ++k) vv[k] = col[lane + 32 * k];
            float cr = 0.f, ci = 0.f;
#pragma unroll
            for (int k = 0; k < 16; ++k) {
                float2 qm = qc[lane + 32 * k];
                cr += qm.x * vv[k].x + qm.y * vv[k].y;                 // conj(q) * v
                ci += qm.x * vv[k].y - qm.y * vv[k].x;
            }
#pragma unroll
            for (int off = 16; off; off >>= 1) {
                cr += __shfl_xor_sync(0xffffffffu, cr, off);
                ci += __shfl_xor_sync(0xffffffffu, ci, off);
            }
            if (j == i + 1) {
                float nr = 0.f;
#pragma unroll
                for (int k = 0; k < 16; ++k) {
                    float2 qm = qc[lane + 32 * k];
                    vv[k].x -= cr * qm.x - ci * qm.y;
                    vv[k].y -= cr * qm.y + ci * qm.x;
                    nr += vv[k].x * vv[k].x + vv[k].y * vv[k].y;
                }
#pragma unroll
                for (int off = 16; off; off >>= 1) nr += __shfl_xor_sync(0xffffffffu, nr, off);
                float inv = 1.f / sqrtf(nr + 1e-8f);
#pragma unroll
                for (int k = 0; k < 16; ++k) {
                    int m = lane + 32 * k;
                    float2 qv = make_float2(vv[k].x * inv, vv[k].y * inv);
                    qn[m] = qv;
                    outp[m * 128 + (i + 1)] = qv;
                }
            } else {
#pragma unroll
                for (int k = 0; k < 16; ++k) {
                    float2 qm = qc[lane + 32 * k];
                    vv[k].x -= cr * qm.x - ci * qm.y;
                    vv[k].y -= cr * qm.y + ci * qm.x;
                    col[lane + 32 * k] = vv[k];
                }
            }
        }
        __syncthreads();
    }
}

// ---------------- launch ----------------
extern "C" void kernel_launch(void* const* d_in, const int* in_sizes, int n_in,
                              void* d_out, int out_size) {
    const float* x   = (const float*)d_in[0];
    const float* cw1 = (const float*)d_in[1];  const float* cb1 = (const float*)d_in[2];
    const float* cw2 = (const float*)d_in[3];  const float* cb2 = (const float*)d_in[4];
    const float* cw3 = (const float*)d_in[5];  const float* cb3 = (const float*)d_in[6];
    const float* fw1 = (const float*)d_in[7];  const float* fb1 = (const float*)d_in[8];
    const float* fw2 = (const float*)d_in[9];  const float* fb2 = (const float*)d_in[10];
    const float* sw1 = (const float*)d_in[11]; const float* sb1 = (const float*)d_in[12];
    const float* sw2 = (const float*)d_in[13]; const float* sb2 = (const float*)d_in[14];
    const float* uw1 = (const float*)d_in[15]; const float* ub1 = (const float*)d_in[16];
    const float* uw2 = (const float*)d_in[17]; const float* ub2 = (const float*)d_in[18];
    const float* vw1 = (const float*)d_in[19]; const float* vb1 = (const float*)d_in[20];
    const float* vw2 = (const float*)d_in[21]; const float* vb2 = (const float*)d_in[22];
    float* out = (float*)d_out;

    float *xchw, *h1, *h2, *h2p, *h3, *feat, *u1, *v1;
    float2 *Ut, *Vt;
    cudaGetSymbolAddress((void**)&xchw, g_xchw);
    cudaGetSymbolAddress((void**)&h1,   g_h1);
    cudaGetSymbolAddress((void**)&h2,   g_h2);
    cudaGetSymbolAddress((void**)&h2p,  g_h2p);
    cudaGetSymbolAddress((void**)&h3,   g_h3);
    cudaGetSymbolAddress((void**)&feat, g_feat);
    cudaGetSymbolAddress((void**)&u1,   g_u1);
    cudaGetSymbolAddress((void**)&v1,   g_v1);
    cudaGetSymbolAddress((void**)&Ut,   g_Ut);
    cudaGetSymbolAddress((void**)&Vt,   g_Vt);

    const int cmm_smem = CMM_SMEM_FLOATS * 4;   // 76352 B
    cudaFuncSetAttribute(conv3x3_mma<32>, cudaFuncAttributeMaxDynamicSharedMemorySize, cmm_smem);
    cudaFuncSetAttribute(conv3x3_mma<64>, cudaFuncAttributeMaxDynamicSharedMemorySize, cmm_smem);

    prep_x_kernel<<<1024, 256>>>(x, xchw);
    conv3x3_relu<2><<<dim3(2, 512, 2), 128, 16 * 2 * 9 * 4>>>(xchw, cw1, cb1, h1, 512, 512);
    conv3x3_mma<32><<<dim3(4, 512, 1), 256, cmm_smem>>>(h1,  cw2, cb2, h2, 512, 512);
    maxpool2_kernel<<<16384, 256>>>(h2, h2p);
    conv3x3_mma<64><<<dim3(2, 256, 2), 256, cmm_smem>>>(h2p, cw3, cb3, h3, 256, 256);
    avgpool_kernel<<<128, 256>>>(h3, feat);
    small_layers_kernel<<<1, 512>>>(feat, fw1, fb1, fw2, fb2, sw1, sb1, sw2, sb2,
                                    uw1, ub1, vw1, vb1, u1, v1, out + 131072);
    big_head_kernel<<<2048, 256>>>(uw2, ub2, vw2, vb2, u1, v1, (float*)Ut, (float*)Vt);
    gs_kernel<<<2, 1024>>>(Ut, Vt, out);
}

// round 14
// speedup vs baseline: 2.2999x; 1.9270x over previous
#include <cuda_runtime.h>
#include <cstdint>
#include <cstddef>

// ---------------- scratch (static __device__ arrays; no cudaMalloc) ----------------
static __device__ float  g_xchw[2 * 512 * 512];
static __device__ float  g_h1 [32 * 512 * 512];
static __device__ float  g_h2p[64 * 256 * 256];
static __device__ float  g_h3 [128 * 256 * 256];
static __device__ float  g_feat[128];
static __device__ float  g_f2[512];
static __device__ float  g_u1[512];
static __device__ float  g_v1[512];
static __device__ float2 g_Ut[128 * 512];      // column-contiguous: [r][m]
static __device__ float2 g_Vt[128 * 512];
static __device__ float2 g_G [2 * 128 * 128];  // FULL Gram matrices
static __device__ float2 g_W [2 * 128 * 128];  // MGS transform: Q = A * W (cols t_j)

// ---------------- (H,W,2) -> CHW transpose ----------------
__global__ void prep_x_kernel(const float* __restrict__ x, float* __restrict__ xchw) {
    int idx = blockIdx.x * 256 + threadIdx.x;   // 512*512 exactly
    float2 v = reinterpret_cast<const float2*>(x)[idx];
    xchw[idx] = v.x;
    xchw[512 * 512 + idx] = v.y;
}

// ---------------- scalar direct conv (used only for tiny conv1, CIN=2) ------------
template<int CIN>
__global__ __launch_bounds__(128)
void conv3x3_relu(const float* __restrict__ in, const float* __restrict__ wt,
                  const float* __restrict__ bias, float* __restrict__ out,
                  int H, int W) {
    extern __shared__ float sw[];               // 16 * CIN * 9 floats
    const int tid = threadIdx.x;
    const int obase = blockIdx.z * 16;
    for (int idx = tid; idx < 16 * CIN * 9; idx += 128)
        sw[idx] = wt[obase * CIN * 9 + idx];
    __syncthreads();

    const int og = tid >> 6;
    const int pg = tid & 63;
    const int h  = blockIdx.y;
    const int x0 = blockIdx.x * 256 + pg * 4;

    float acc[8][4];
#pragma unroll
    for (int a = 0; a < 8; ++a)
#pragma unroll
        for (int p = 0; p < 4; ++p) acc[a][p] = 0.f;

#pragma unroll
    for (int c = 0; c < CIN; ++c) {
#pragma unroll
        for (int ky = 0; ky < 3; ++ky) {
            const int yy = h + ky - 1;
            const bool yv = ((unsigned)yy < (unsigned)H);
            const float* ip = in + ((size_t)c * H + yy) * W;
            float r[6];
#pragma unroll
            for (int dx = 0; dx < 6; ++dx) {
                int xx = x0 - 1 + dx;
                r[dx] = (yv && (unsigned)xx < (unsigned)W) ? __ldg(ip + xx) : 0.f;
            }
            const float* swp = sw + (og * 8) * (CIN * 9) + c * 9 + ky * 3;
#pragma unroll
            for (int kx = 0; kx < 3; ++kx) {
#pragma unroll
                for (int oo = 0; oo < 8; ++oo) {
                    float wv = swp[oo * (CIN * 9) + kx];
                    acc[oo][0] = fmaf(wv, r[kx + 0], acc[oo][0]);
                    acc[oo][1] = fmaf(wv, r[kx + 1], acc[oo][1]);
                    acc[oo][2] = fmaf(wv, r[kx + 2], acc[oo][2]);
                    acc[oo][3] = fmaf(wv, r[kx + 3], acc[oo][3]);
                }
            }
        }
    }
#pragma unroll
    for (int oo = 0; oo < 8; ++oo) {
        const int o = obase + og * 8 + oo;
        const float b = bias[o];
        float4 res;
        res.x = fmaxf(acc[oo][0] + b, 0.f); res.y = fmaxf(acc[oo][1] + b, 0.f);
        res.z = fmaxf(acc[oo][2] + b, 0.f); res.w = fmaxf(acc[oo][3] + b, 0.f);
        *reinterpret_cast<float4*>(out + ((size_t)o * H + h) * W + x0) = res;
    }
}

// ---------------- tf32 helpers ----------------
__device__ __forceinline__ float tf32r(float v) {
    uint32_t r;
    asm("cvt.rna.tf32.f32 %0, %1;" : "=r"(r) : "f"(v));
    return __uint_as_float(r);
}
__device__ __forceinline__ void mma_tf32(float* c, uint32_t a0, uint32_t a1,
                                         uint32_t a2, uint32_t a3,
                                         uint32_t b0, uint32_t b1) {
    asm volatile(
        "mma.sync.aligned.m16n8k8.row.col.f32.tf32.tf32.f32 "
        "{%0,%1,%2,%3}, {%4,%5,%6,%7}, {%8,%9}, {%0,%1,%2,%3};"
        : "+f"(c[0]), "+f"(c[1]), "+f"(c[2]), "+f"(c[3])
        : "r"(a0), "r"(a1), "r"(a2), "r"(a3), "r"(b0), "r"(b1));
}
__device__ __forceinline__ uint32_t fbits(float v) { return __float_as_uint(v); }

// ---------------- conv2 (32->64) tf32 MMA, fused 2x2 maxpool ----------------
// smem floats: xh[4][130][12]=6240 | xl 6240 | wh[64][76]=4864 | wl 4864 = 22208
#define C2P_SMEM_FLOATS 22208
__global__ __launch_bounds__(256)
void conv2_mma_pool(const float* __restrict__ in, const float* __restrict__ wt,
                    const float* __restrict__ bias, float* __restrict__ out) {
    extern __shared__ float sm[];
    float* xh = sm;
    float* xl = sm + 6240;
    float* wh = sm + 12480;
    float* wl = sm + 17344;

    const int t = threadIdx.x;
    const int lane = t & 31, warp = t >> 5;
    const int g = lane >> 2, tg = lane & 3;
    const int mwarp = warp & 3, nwarp = warp >> 2;
    const int x0 = blockIdx.x * 128;
    const int y0 = blockIdx.y * 2;

    float acc[2][8][4];
#pragma unroll
    for (int ry = 0; ry < 2; ++ry)
#pragma unroll
        for (int nt = 0; nt < 8; ++nt)
#pragma unroll
            for (int i = 0; i < 4; ++i) acc[ry][nt][i] = 0.f;

#pragma unroll 1
    for (int c0 = 0; c0 < 4; ++c0) {    // 32 in-ch / 8
        __syncthreads();
        for (int idx = t; idx < 4160; idx += 256) {
            int c  = idx / 520;
            int rr = idx - c * 520;
            int r  = rr / 130, x = rr - r * 130;
            int yy = y0 + r - 1, xx = x0 + x - 1;
            float v = 0.f;
            if ((unsigned)yy < 512u && (unsigned)xx < 512u)
                v = __ldg(in + ((size_t)(c0 * 8 + c) * 512 + yy) * 512 + xx);
            float hi = tf32r(v);
            float lo = tf32r(v - hi);
            int o = (r * 130 + x) * 12 + c;
            xh[o] = hi; xl[o] = lo;
        }
        for (int idx = t; idx < 4608; idx += 256) {
            int o = idx / 72, r = idx - o * 72;
            int s = r >> 3, k = r & 7;
            float v = __ldg(wt + ((size_t)o * 32 + c0 * 8 + k) * 9 + s);
            float hi = tf32r(v);
            float lo = tf32r(v - hi);
            wh[o * 76 + s * 8 + k] = hi;
            wl[o * 76 + s * 8 + k] = lo;
        }
        __syncthreads();

#pragma unroll
        for (int ky = 0; ky < 3; ++ky) {
#pragma unroll
            for (int kx = 0; kx < 3; ++kx) {
                const int s = ky * 3 + kx;
                const float* pwh = wh + (mwarp * 16 + g) * 76 + s * 8 + tg;
                const float* pwl = wl + (mwarp * 16 + g) * 76 + s * 8 + tg;
                uint32_t a0h = fbits(pwh[0]),      a2h = fbits(pwh[4]);
                uint32_t a1h = fbits(pwh[8 * 76]), a3h = fbits(pwh[8 * 76 + 4]);
                uint32_t a0l = fbits(pwl[0]),      a2l = fbits(pwl[4]);
                uint32_t a1l = fbits(pwl[8 * 76]), a3l = fbits(pwl[8 * 76 + 4]);
#pragma unroll
                for (int ry = 0; ry < 2; ++ry) {
                    const int xbase = ((ky + ry) * 130 + nwarp * 64 + g + kx) * 12 + tg;
#pragma unroll
                    for (int nt = 0; nt < 8; ++nt) {
                        const int ib = xbase + nt * 96;
                        uint32_t b0h = fbits(xh[ib]), b1h = fbits(xh[ib + 4]);
                        uint32_t b0l = fbits(xl[ib]), b1l = fbits(xl[ib + 4]);
                        mma_tf32(acc[ry][nt], a0h, a1h, a2h, a3h, b0h, b1h);
                        mma_tf32(acc[ry][nt], a0l, a1l, a2l, a3l, b0h, b1h);
                        mma_tf32(acc[ry][nt], a0h, a1h, a2h, a3h, b0l, b1l);
                    }
                }
            }
        }
    }

    const int o_lo = mwarp * 16 + g;
    const float b_lo = __ldg(bias + o_lo);
    const float b_hi = __ldg(bias + o_lo + 8);
    float* rowp_lo = out + ((size_t)o_lo * 256 + blockIdx.y) * 256;
    float* rowp_hi = out + ((size_t)(o_lo + 8) * 256 + blockIdx.y) * 256;
#pragma unroll
    for (int nt = 0; nt < 8; ++nt) {
        int xp = x0 / 2 + nwarp * 32 + nt * 4 + tg;
        float l00 = fmaxf(acc[0][nt][0] + b_lo, 0.f), l01 = fmaxf(acc[0][nt][1] + b_lo, 0.f);
        float l10 = fmaxf(acc[1][nt][0] + b_lo, 0.f), l11 = fmaxf(acc[1][nt][1] + b_lo, 0.f);
        rowp_lo[xp] = fmaxf(fmaxf(l00, l01), fmaxf(l10, l11));
        float h00 = fmaxf(acc[0][nt][2] + b_hi, 0.f), h01 = fmaxf(acc[0][nt][3] + b_hi, 0.f);
        float h10 = fmaxf(acc[1][nt][2] + b_hi, 0.f), h11 = fmaxf(acc[1][nt][3] + b_hi, 0.f);
        rowp_hi[xp] = fmaxf(fmaxf(h00, h01), fmaxf(h10, h11));
    }
}

// ---------------- conv3 tf32 MMA ----------------
// smem floats: xh[3][130][12]=4680 | xl | wh[64][76]=4864 | wl = 19088
#define CMM_SMEM_FLOATS 19088
template<int CIN>
__global__ __launch_bounds__(256)
void conv3x3_mma(const float* __restrict__ in, const float* __restrict__ wt,
                 const float* __restrict__ bias, float* __restrict__ out,
                 int H, int W) {
    extern __shared__ float sm[];
    float* xh = sm;
    float* xl = sm + 4680;
    float* wh = sm + 9360;
    float* wl = sm + 14224;

    const int t = threadIdx.x;
    const int lane = t & 31, warp = t >> 5;
    const int g = lane >> 2, tg = lane & 3;
    const int mwarp = warp & 3, nwarp = warp >> 2;
    const int x0 = blockIdx.x * 128;
    const int y  = blockIdx.y;
    const int obase = blockIdx.z * 64;

    float acc[8][4];
#pragma unroll
    for (int nt = 0; nt < 8; ++nt)
#pragma unroll
        for (int i = 0; i < 4; ++i) acc[nt][i] = 0.f;

#pragma unroll 1
    for (int c0 = 0; c0 < CIN / 8; ++c0) {
        __syncthreads();
        for (int idx = t; idx < 3120; idx += 256) {
            int c  = idx / 390;
            int rr = idx - c * 390;
            int r  = rr / 130, x = rr - r * 130;
            int yy = y + r - 1, xx = x0 + x - 1;
            float v = 0.f;
            if ((unsigned)yy < (unsigned)H && (unsigned)xx < (unsigned)W)
                v = __ldg(in + ((size_t)(c0 * 8 + c) * H + yy) * W + xx);
            float hi = tf32r(v);
            float lo = tf32r(v - hi);
            int o = (r * 130 + x) * 12 + c;
            xh[o] = hi; xl[o] = lo;
        }
        for (int idx = t; idx < 4608; idx += 256) {
            int o = idx / 72, r = idx - o * 72;
            int s = r >> 3, k = r & 7;
            float v = __ldg(wt + ((size_t)(obase + o) * CIN + c0 * 8 + k) * 9 + s);
            float hi = tf32r(v);
            float lo = tf32r(v - hi);
            wh[o * 76 + s * 8 + k] = hi;
            wl[o * 76 + s * 8 + k] = lo;
        }
        __syncthreads();

#pragma unroll
        for (int ky = 0; ky < 3; ++ky) {
#pragma unroll
            for (int kx = 0; kx < 3; ++kx) {
                const int s = ky * 3 + kx;
                const float* pwh = wh + (mwarp * 16 + g) * 76 + s * 8 + tg;
                const float* pwl = wl + (mwarp * 16 + g) * 76 + s * 8 + tg;
                uint32_t a0h = fbits(pwh[0]),      a2h = fbits(pwh[4]);
                uint32_t a1h = fbits(pwh[8 * 76]), a3h = fbits(pwh[8 * 76 + 4]);
                uint32_t a0l = fbits(pwl[0]),      a2l = fbits(pwl[4]);
                uint32_t a1l = fbits(pwl[8 * 76]), a3l = fbits(pwl[8 * 76 + 4]);
                const int xbase = (ky * 130 + nwarp * 64 + g + kx) * 12 + tg;
#pragma unroll
                for (int nt = 0; nt < 8; ++nt) {
                    const int ib = xbase + nt * 96;
                    uint32_t b0h = fbits(xh[ib]), b1h = fbits(xh[ib + 4]);
                    uint32_t b0l = fbits(xl[ib]), b1l = fbits(xl[ib + 4]);
                    mma_tf32(acc[nt], a0h, a1h, a2h, a3h, b0h, b1h);
                    mma_tf32(acc[nt], a0l, a1l, a2l, a3l, b0h, b1h);
                    mma_tf32(acc[nt], a0h, a1h, a2h, a3h, b0l, b1l);
                }
            }
        }
    }

    const int o_lo = obase + mwarp * 16 + g;
    const float b_lo = __ldg(bias + o_lo);
    const float b_hi = __ldg(bias + o_lo + 8);
    float* row_lo = out + ((size_t)o_lo * H + y) * W;
    float* row_hi = out + ((size_t)(o_lo + 8) * H + y) * W;
#pragma unroll
    for (int nt = 0; nt < 8; ++nt) {
        int x = x0 + nwarp * 64 + nt * 8 + 2 * tg;
        float2 v0 = make_float2(fmaxf(acc[nt][0] + b_lo, 0.f),
                                fmaxf(acc[nt][1] + b_lo, 0.f));
        float2 v1 = make_float2(fmaxf(acc[nt][2] + b_hi, 0.f),
                                fmaxf(acc[nt][3] + b_hi, 0.f));
        *reinterpret_cast<float2*>(row_lo + x) = v0;
        *reinterpret_cast<float2*>(row_hi + x) = v1;
    }
}

// ---------------- global average pool: 128 channels of 256x256 ----------------
__global__ void avgpool_kernel(const float* __restrict__ in, float* __restrict__ feat) {
    const int c = blockIdx.x;
    const float* p = in + (size_t)c * 65536;
    float s = 0.f;
    for (int i = threadIdx.x; i < 65536; i += 256) s += p[i];
    __shared__ float sh[256];
    sh[threadIdx.x] = s;
    __syncthreads();
    for (int off = 128; off > 0; off >>= 1) {
        if (threadIdx.x < off) sh[threadIdx.x] += sh[threadIdx.x + off];
        __syncthreads();
    }
    if (threadIdx.x == 0) feat[c] = sh[0] * (1.f / 65536.f);
}

// ---------------- fused small FC trunk + s head (softplus+sort); exports f2 ----------
__device__ __forceinline__ float dot4(const float* __restrict__ w,
                                      const float* __restrict__ v, int n4) {
    float a = 0.f;
    const float4* w4 = (const float4*)w;
    const float4* v4 = (const float4*)v;
#pragma unroll 8
    for (int k = 0; k < n4; ++k) {
        float4 ww = w4[k], vv = v4[k];
        a += ww.x * vv.x + ww.y * vv.y + ww.z * vv.z + ww.w * vv.w;
    }
    return a;
}

__global__ __launch_bounds__(512)
void small_layers_kernel(const float* __restrict__ feat,
    const float* __restrict__ fw1, const float* __restrict__ fb1,
    const float* __restrict__ fw2, const float* __restrict__ fb2,
    const float* __restrict__ sw1, const float* __restrict__ sb1,
    const float* __restrict__ sw2, const float* __restrict__ sb2,
    float* __restrict__ f2g, float* __restrict__ s_out) {
    __shared__ __align__(16) float sf[128];
    __shared__ __align__(16) float f1[256];
    __shared__ __align__(16) float f2[512];
    __shared__ __align__(16) float s1[256];
    __shared__ float sv[128];
    const int t = threadIdx.x;

    if (t < 128) sf[t] = feat[t];
    __syncthreads();

    if (t < 256) f1[t] = fmaxf(fb1[t] + dot4(fw1 + t * 128, sf, 32), 0.f);
    __syncthreads();

    {
        float val = fmaxf(fb2[t] + dot4(fw2 + t * 256, f1, 64), 0.f);
        f2[t] = val;
        f2g[t] = val;
    }
    __syncthreads();

    if (t < 256) s1[t] = fmaxf(sb1[t] + dot4(sw1 + (size_t)t * 512, f2, 128), 0.f);
    __syncthreads();

    if (t < 128) {
        float xv = sb2[t] + dot4(sw2 + t * 256, s1, 64);
        sv[t] = (xv > 0.f) ? (xv + log1pf(expf(-xv))) : log1pf(expf(xv));
    }
    __syncthreads();

    if (t < 128) {
        float v = sv[t];
        int rank = 0;
        for (int j = 0; j < 128; ++j) {
            float o = sv[j];
            rank += (o > v) || (o == v && j > t);
        }
        s_out[rank] = v;
    }
}

// ---------------- u1/v1 matvecs in parallel (1024 warps) ----------------
__global__ __launch_bounds__(256)
void u1v1_kernel(const float* __restrict__ uw1, const float* __restrict__ ub1,
                 const float* __restrict__ vw1, const float* __restrict__ vb1,
                 const float* __restrict__ f2g,
                 float* __restrict__ u1, float* __restrict__ v1) {
    __shared__ __align__(16) float sf[512];
    const int t = threadIdx.x;
    sf[t] = f2g[t]; sf[t + 256] = f2g[t + 256];
    __syncthreads();
    const int lane = t & 31, warp = t >> 5;
    const int row = blockIdx.x * 8 + warp;          // 0..1023
    const float* wrow;
    float b; float* dst;
    if (row < 512) { wrow = uw1 + (size_t)row * 512; b = ub1[row]; dst = u1 + row; }
    else { wrow = vw1 + (size_t)(row - 512) * 512; b = vb1[row - 512]; dst = v1 + (row - 512); }
    float a = 0.f;
    const float4* w4 = (const float4*)wrow;
    const float4* x4 = (const float4*)sf;
#pragma unroll
    for (int k = lane; k < 128; k += 32) {
        float4 ww = w4[k], vv = x4[k];
        a += ww.x * vv.x + ww.y * vv.y + ww.z * vv.z + ww.w * vv.w;
    }
#pragma unroll
    for (int off = 16; off; off >>= 1) a += __shfl_down_sync(0xffffffffu, a, off);
    if (lane == 0) *dst = fmaxf(a + b, 0.f);
}

// ---------------- big head matvecs: 2 x (131072 x 512), write transposed ----------------
__global__ __launch_bounds__(256)
void big_head_kernel(const float* __restrict__ uw2, const float* __restrict__ ub2,
                     const float* __restrict__ vw2, const float* __restrict__ vb2,
                     const float* __restrict__ u1, const float* __restrict__ v1,
                     float* __restrict__ Ut, float* __restrict__ Vt) {
    __shared__ __align__(16) float su[512];
    __shared__ __align__(16) float svv[512];
    const int t = threadIdx.x;
    for (int i = t; i < 512; i += 256) { su[i] = u1[i]; svv[i] = v1[i]; }
    __syncthreads();

    const int lane = t & 31, warp = t >> 5;
    const int gw = blockIdx.x * 8 + warp;
#pragma unroll 1
    for (int rr = 0; rr < 16; ++rr) {
        int e = gw * 16 + rr;
        const float* wrow; const float* xv; float b; float* dst;
        if (e < 131072) {
            wrow = uw2 + (size_t)e * 512; xv = su; b = ub2[e];
            int m = e >> 8, r = (e >> 1) & 127, cp = e & 1;
            dst = Ut + (size_t)(r * 512 + m) * 2 + cp;
        } else {
            int e2 = e - 131072;
            wrow = vw2 + (size_t)e2 * 512; xv = svv; b = vb2[e2];
            int m = e2 >> 8, r = (e2 >> 1) & 127, cp = e2 & 1;
            dst = Vt + (size_t)(r * 512 + m) * 2 + cp;
        }
        float a = 0.f;
        const float4* w4 = (const float4*)wrow;
        const float4* x4 = (const float4*)xv;
#pragma unroll
        for (int k = lane; k < 128; k += 32) {
            float4 ww = w4[k], vv = x4[k];
            a += ww.x * vv.x + ww.y * vv.y + ww.z * vv.z + ww.w * vv.w;
        }
#pragma unroll
        for (int off = 16; off; off >>= 1) a += __shfl_down_sync(0xffffffffu, a, off);
        if (lane == 0) *dst = a + b;
    }
}

// ---------------- Gram: G = A^H A (FULL matrix) ------------------------------------
__global__ __launch_bounds__(256)
void gram_kernel(const float2* __restrict__ A0, const float2* __restrict__ A1,
                 float2* __restrict__ G) {
    const float2* A = (blockIdx.y == 0) ? A0 : A1;
    float2* Gm = G + blockIdx.y * 128 * 128;
    const int p = blockIdx.x;
    const int lane = threadIdx.x & 31, warp = threadIdx.x >> 5;
    const float2* ap = A + (size_t)p * 512;
    for (int q = warp; q < 128; q += 8) {
        const float2* aq = A + (size_t)q * 512;
        float cr = 0.f, ci = 0.f;
#pragma unroll
        for (int k = 0; k < 16; ++k) {
            float2 xp = ap[lane + 32 * k], xq = aq[lane + 32 * k];
            cr += xp.x * xq.x + xp.y * xq.y;    // re(conj(a_p) . a_q)
            ci += xp.x * xq.y - xp.y * xq.x;    // im
        }
#pragma unroll
        for (int off = 16; off; off >>= 1) {
            cr += __shfl_xor_sync(0xffffffffu, cr, off);
            ci += __shfl_xor_sync(0xffffffffu, ci, off);
        }
        if (lane == 0) Gm[p * 128 + q] = make_float2(cr, ci);
    }
}

// ---------------- Gram-space MGS with eps (EXACT reference semantics) --------------
// One block per matrix, 1024 threads = 32 warps. Warp w owns cols {w, w+32, w+64, w+96}
// (register-resident coefficient vectors); lane l owns rows {l, l+32, l+64, l+96}.
// U = G*V lives in smem; per step: normalize col i (t_i = v_i/sqrt(v_i^H u_i + 1e-8)),
// publish t_i & G t_i, then every later column does the MGS update. Output: W cols = t_j.
#define GSG_SMEM_BYTES (128 * 130 * 8 + 2 * 128 * 8)
__global__ __launch_bounds__(1024, 1)
void gsgram_kernel(const float2* __restrict__ G, float2* __restrict__ gW) {
    extern __shared__ float2 sm2[];
    float2* sU  = sm2;                 // [col][row], row stride 1, col stride 130
    float2* sT  = sm2 + 128 * 130;     // t_i broadcast
    float2* sGT = sT + 128;            // (G t_i) broadcast
    const float2* Gm = G + blockIdx.x * 128 * 128;
    float2* Wm = gW + blockIdx.x * 128 * 128;
    const int t = threadIdx.x, lane = t & 31, warp = t >> 5;

    // load U: u_j = G[:, j]
    for (int idx = t; idx < 16384; idx += 1024) {
        int r = idx >> 7, j = idx & 127;          // coalesced read of Gm row r
        sU[j * 130 + r] = Gm[r * 128 + j];
    }

    // V init = I (coefficient vectors in registers)
    float2 v[4][4];                                // [colslot][rowslot]
#pragma unroll
    for (int cs = 0; cs < 4; ++cs)
#pragma unroll
        for (int rs = 0; rs < 4; ++rs) v[cs][rs] = make_float2(0.f, 0.f);
    if (lane == warp) {
#pragma unroll
        for (int cs = 0; cs < 4; ++cs) v[cs][cs] = make_float2(1.f, 0.f);
    }
    __syncthreads();

#pragma unroll 1
    for (int i = 0; i < 128; ++i) {
        const int iw = i & 31, is = i >> 5;
        if (warp == iw) {
            // d2 = Re(v_i^H u_i)  (exact |v_i|^2 in vector space)
            float d2 = 0.f;
#pragma unroll
            for (int rs = 0; rs < 4; ++rs) {
                float2 vv = v[is][rs];
                float2 uu = sU[i * 130 + lane + 32 * rs];
                d2 += vv.x * uu.x + vv.y * uu.y;
            }
#pragma unroll
            for (int off = 16; off; off >>= 1) d2 += __shfl_xor_sync(0xffffffffu, d2, off);
            const float inv = 1.f / sqrtf(d2 + 1e-8f);   // reference epsilon, exactly
#pragma unroll
            for (int rs = 0; rs < 4; ++rs) {
                int r = lane + 32 * rs;
                float2 vv = v[is][rs];
                float2 tv = make_float2(vv.x * inv, vv.y * inv);
                sT[r] = tv;
                Wm[i * 128 + r] = tv;                    // column t_i of transform
                float2 uu = sU[i * 130 + r];
                sGT[r] = make_float2(uu.x * inv, uu.y * inv);
            }
        }
        __syncthreads();
        // MGS update of all later columns: c = t_i^H u_j; v_j -= c t_i; u_j -= c (G t_i)
#pragma unroll
        for (int cs = 0; cs < 4; ++cs) {
            const int j = warp + 32 * cs;
            if (j > i) {
                float cr = 0.f, ci = 0.f;
#pragma unroll
                for (int rs = 0; rs < 4; ++rs) {
                    int r = lane + 32 * rs;
                    float2 tt = sT[r];
                    float2 uu = sU[j * 130 + r];
                    cr += tt.x * uu.x + tt.y * uu.y;     // conj(t) . u
                    ci += tt.x * uu.y - tt.y * uu.x;
                }
#pragma unroll
                for (int off = 16; off; off >>= 1) {
                    cr += __shfl_xor_sync(0xffffffffu, cr, off);
                    ci += __shfl_xor_sync(0xffffffffu, ci, off);
                }
#pragma unroll
                for (int rs = 0; rs < 4; ++rs) {
                    int r = lane + 32 * rs;
                    float2 tt = sT[r];
                    v[cs][rs].x -= cr * tt.x - ci * tt.y;
                    v[cs][rs].y -= cr * tt.y + ci * tt.x;
                    float2 gg = sGT[r];
                    float2 uu = sU[j * 130 + r];
                    uu.x -= cr * gg.x - ci * gg.y;
                    uu.y -= cr * gg.y + ci * gg.x;
                    sU[j * 130 + r] = uu;
                }
            }
        }
        __syncthreads();
    }
}

// ---------------- apply: Q = A * W, write (m, r, 2) output layout -------------------
__global__ __launch_bounds__(256)
void apply_kernel(const float2* __restrict__ A0, const float2* __restrict__ A1,
                  const float2* __restrict__ gW, float* __restrict__ out) {
    const int mat = blockIdx.y;
    const float2* A = (mat == 0) ? A0 : A1;
    const float2* W = gW + mat * 128 * 128;
    float2* outp = (float2*)(out + ((mat == 0) ? 0 : (131072 + 128)));
    const int lane = threadIdx.x & 31, warp = threadIdx.x >> 5;
    const int j = blockIdx.x * 8 + warp;

    float2 acc[16];
#pragma unroll
    for (int s = 0; s < 16; ++s) acc[s] = make_float2(0.f, 0.f);

#pragma unroll 1
    for (int k = 0; k <= j; ++k) {                // t_j support: rows 0..j
        float2 w = __ldg(&W[j * 128 + k]);
        const float2* ak = A + (size_t)k * 512;
#pragma unroll
        for (int s = 0; s < 16; ++s) {
            float2 a = ak[lane + 32 * s];
            acc[s].x += w.x * a.x - w.y * a.y;
            acc[s].y += w.x * a.y + w.y * a.x;
        }
    }
#pragma unroll
    for (int s = 0; s < 16; ++s)
        outp[(size_t)(lane + 32 * s) * 128 + j] = acc[s];
}

// ---------------- launch ----------------
extern "C" void kernel_launch(void* const* d_in, const int* in_sizes, int n_in,
                              void* d_out, int out_size) {
    const float* x   = (const float*)d_in[0];
    const float* cw1 = (const float*)d_in[1];  const float* cb1 = (const float*)d_in[2];
    const float* cw2 = (const float*)d_in[3];  const float* cb2 = (const float*)d_in[4];
    const float* cw3 = (const float*)d_in[5];  const float* cb3 = (const float*)d_in[6];
    const float* fw1 = (const float*)d_in[7];  const float* fb1 = (const float*)d_in[8];
    const float* fw2 = (const float*)d_in[9];  const float* fb2 = (const float*)d_in[10];
    const float* sw1 = (const float*)d_in[11]; const float* sb1 = (const float*)d_in[12];
    const float* sw2 = (const float*)d_in[13]; const float* sb2 = (const float*)d_in[14];
    const float* uw1 = (const float*)d_in[15]; const float* ub1 = (const float*)d_in[16];
    const float* uw2 = (const float*)d_in[17]; const float* ub2 = (const float*)d_in[18];
    const float* vw1 = (const float*)d_in[19]; const float* vb1 = (const float*)d_in[20];
    const float* vw2 = (const float*)d_in[21]; const float* vb2 = (const float*)d_in[22];
    float* out = (float*)d_out;

    float *xchw, *h1, *h2p, *h3, *feat, *f2g, *u1, *v1;
    float2 *Ut, *Vt, *G, *W;
    cudaGetSymbolAddress((void**)&xchw, g_xchw);
    cudaGetSymbolAddress((void**)&h1,   g_h1);
    cudaGetSymbolAddress((void**)&h2p,  g_h2p);
    cudaGetSymbolAddress((void**)&h3,   g_h3);
    cudaGetSymbolAddress((void**)&feat, g_feat);
    cudaGetSymbolAddress((void**)&f2g,  g_f2);
    cudaGetSymbolAddress((void**)&u1,   g_u1);
    cudaGetSymbolAddress((void**)&v1,   g_v1);
    cudaGetSymbolAddress((void**)&Ut,   g_Ut);
    cudaGetSymbolAddress((void**)&Vt,   g_Vt);
    cudaGetSymbolAddress((void**)&G,    g_G);
    cudaGetSymbolAddress((void**)&W,    g_W);

    const int c2p_smem = C2P_SMEM_FLOATS * 4;   // 88832 B
    const int cmm_smem = CMM_SMEM_FLOATS * 4;   // 76352 B
    const int gsg_smem = GSG_SMEM_BYTES;        // 135168 B
    cudaFuncSetAttribute(conv2_mma_pool, cudaFuncAttributeMaxDynamicSharedMemorySize, c2p_smem);
    cudaFuncSetAttribute(conv3x3_mma<64>, cudaFuncAttributeMaxDynamicSharedMemorySize, cmm_smem);
    cudaFuncSetAttribute(gsgram_kernel, cudaFuncAttributeMaxDynamicSharedMemorySize, gsg_smem);

    prep_x_kernel<<<1024, 256>>>(x, xchw);
    conv3x3_relu<2><<<dim3(2, 512, 2), 128, 16 * 2 * 9 * 4>>>(xchw, cw1, cb1, h1, 512, 512);
    conv2_mma_pool<<<dim3(4, 256, 1), 256, c2p_smem>>>(h1, cw2, cb2, h2p);
    conv3x3_mma<64><<<dim3(2, 256, 2), 256, cmm_smem>>>(h2p, cw3, cb3, h3, 256, 256);
    avgpool_kernel<<<128, 256>>>(h3, feat);
    small_layers_kernel<<<1, 512>>>(feat, fw1, fb1, fw2, fb2, sw1, sb1, sw2, sb2,
                                    f2g, out + 131072);
    u1v1_kernel<<<128, 256>>>(uw1, ub1, vw1, vb1, f2g, u1, v1);
    big_head_kernel<<<2048, 256>>>(uw2, ub2, vw2, vb2, u1, v1, (float*)Ut, (float*)Vt);

    // ---- Gram-space eps-MGS (exact reference semantics) ----
    gram_kernel<<<dim3(128, 2), 256>>>(Ut, Vt, G);
    gsgram_kernel<<<2, 1024, gsg_smem>>>(G, W);
    apply_kernel<<<dim3(16, 2), 256>>>(Ut, Vt, W, out);
}